// round 1
// baseline (speedup 1.0000x reference)
#include <cuda_runtime.h>
#include <math.h>

#define NN   50000
#define NE   600000
#define IND  512
#define HID  128
#define OUTD 64
#define FAEPS 0.1f

// ---------------- scratch (static device memory; no allocs) ----------------
__device__ __align__(256) int   g_cnt[NN];
__device__ __align__(256) int   g_cur[NN];
__device__ __align__(256) int   g_off[NN + 1];
__device__ __align__(256) int   g_csrc[NE];    // src per CSR slot
__device__ __align__(256) int   g_cpos[NE];    // edge e -> CSR slot
__device__ __align__(256) float g_dinv[NN];
__device__ __align__(256) float g_norm[NE];    // per-edge gcn norm (edge order)
__device__ __align__(256) float g_w[NE];       // per-edge weight in CSR order
__device__ __align__(256) float g_h0[NN * HID];  // raw (post transform-1)
__device__ __align__(256) float g_ha[NN * HID];
__device__ __align__(256) float g_hb[NN * HID];
__device__ __align__(256) float g_al[NN];
__device__ __align__(256) float g_ar[NN];

__device__ __forceinline__ float* hsel(int s) {
    return s == 0 ? g_h0 : (s == 1 ? g_ha : g_hb);
}

__device__ __forceinline__ float my_tanh(float x) {
    // 1 - 2/(exp(2x)+1): robust at +/-inf, accurate enough even under fast-math expf
    float e = expf(2.0f * x);
    return 1.0f - 2.0f / (e + 1.0f);
}

// ---------------- graph preprocessing ----------------
__global__ void k_zero() {
    int i = blockIdx.x * blockDim.x + threadIdx.x;
    if (i < NN) { g_cnt[i] = 0; g_cur[i] = 0; }
}

__global__ void k_hist(const int* __restrict__ dst) {
    int e = blockIdx.x * blockDim.x + threadIdx.x;
    if (e < NE) atomicAdd(&g_cnt[dst[e]], 1);
}

// single-block exclusive scan over g_cnt -> g_off
__global__ void k_scan() {
    __shared__ int sums[1024];
    int tid = threadIdx.x;
    int chunk = (NN + 1023) / 1024;
    int beg = tid * chunk;
    int end = beg + chunk; if (end > NN) end = NN;
    int s = 0;
    for (int i = beg; i < end && i < NN; i++) s += g_cnt[i];
    sums[tid] = s;
    __syncthreads();
    for (int off = 1; off < 1024; off <<= 1) {
        int v = 0;
        if (tid >= off) v = sums[tid - off];
        __syncthreads();
        sums[tid] += v;
        __syncthreads();
    }
    int run = (tid == 0) ? 0 : sums[tid - 1];
    for (int i = beg; i < end && i < NN; i++) { g_off[i] = run; run += g_cnt[i]; }
    if (tid == 1023) g_off[NN] = sums[1023];
}

__global__ void k_dinv() {
    int i = blockIdx.x * blockDim.x + threadIdx.x;
    if (i < NN) {
        int c = g_cnt[i];
        g_dinv[i] = (c > 0) ? rsqrtf((float)c) : 0.0f;
    }
}

__global__ void k_fill(const int* __restrict__ src, const int* __restrict__ dst) {
    int e = blockIdx.x * blockDim.x + threadIdx.x;
    if (e >= NE) return;
    int s = src[e], d = dst[e];
    int slot = atomicAdd(&g_cur[d], 1);
    int k = g_off[d] + slot;
    g_csrc[k] = s;
    g_cpos[e] = k;
    g_norm[e] = g_dinv[s] * g_dinv[d];
}

// ---------------- transform 1: h = relu(x @ W1^T + b1) ----------------
// classic 128x128 tile, BK=8, 256 threads, 8x8 microtile
__global__ void k_gemm1(const float* __restrict__ X, const float* __restrict__ W,
                        const float* __restrict__ B) {
    __shared__ float As[8][128];
    __shared__ float Bs[8][128];
    int tid = threadIdx.x;
    int m0 = blockIdx.x * 128;
    int lr = tid >> 1;            // 0..127
    int lc = (tid & 1) * 4;       // 0 or 4
    int tr = (tid >> 4) * 8;      // 0..120
    int tc = (tid & 15) * 8;      // 0..120

    float acc[8][8];
#pragma unroll
    for (int i = 0; i < 8; i++)
#pragma unroll
        for (int j = 0; j < 8; j++) acc[i][j] = 0.0f;

    for (int k0 = 0; k0 < IND; k0 += 8) {
        float4 av = make_float4(0.f, 0.f, 0.f, 0.f);
        int m = m0 + lr;
        if (m < NN) av = *(const float4*)(X + (size_t)m * IND + k0 + lc);
        As[lc + 0][lr] = av.x; As[lc + 1][lr] = av.y;
        As[lc + 2][lr] = av.z; As[lc + 3][lr] = av.w;
        float4 bv = *(const float4*)(W + (size_t)lr * IND + k0 + lc);
        Bs[lc + 0][lr] = bv.x; Bs[lc + 1][lr] = bv.y;
        Bs[lc + 2][lr] = bv.z; Bs[lc + 3][lr] = bv.w;
        __syncthreads();
#pragma unroll
        for (int kk = 0; kk < 8; kk++) {
            float ra[8], rb[8];
#pragma unroll
            for (int i = 0; i < 8; i++) { ra[i] = As[kk][tr + i]; rb[i] = Bs[kk][tc + i]; }
#pragma unroll
            for (int i = 0; i < 8; i++)
#pragma unroll
                for (int j = 0; j < 8; j++) acc[i][j] = fmaf(ra[i], rb[j], acc[i][j]);
        }
        __syncthreads();
    }
#pragma unroll
    for (int i = 0; i < 8; i++) {
        int m = m0 + tr + i;
        if (m >= NN) continue;
#pragma unroll
        for (int j = 0; j < 8; j++) {
            float v = acc[i][j] + B[tc + j];
            g_h0[(size_t)m * HID + tc + j] = v > 0.0f ? v : 0.0f;
        }
    }
}

// ---------------- per-layer: attention projections al/ar ----------------
// warp per node
__global__ void k_attn(int hin_sel, const float* __restrict__ attl,
                       const float* __restrict__ attr) {
    int gt = blockIdx.x * blockDim.x + threadIdx.x;
    int n = gt >> 5;
    int lane = gt & 31;
    if (n >= NN) return;
    const float4* h4 = (const float4*)hsel(hin_sel);
    float4 hv = h4[(size_t)n * 32 + lane];
    float4 la = *(const float4*)(attl + lane * 4);
    float4 ra = *(const float4*)(attr + lane * 4);
    float pa = hv.x * la.x + hv.y * la.y + hv.z * la.z + hv.w * la.w;
    float pb = hv.x * ra.x + hv.y * ra.y + hv.z * ra.z + hv.w * ra.w;
#pragma unroll
    for (int off = 16; off; off >>= 1) {
        pa += __shfl_xor_sync(0xffffffffu, pa, off);
        pb += __shfl_xor_sync(0xffffffffu, pb, off);
    }
    if (lane == 0) { g_al[n] = pa; g_ar[n] = pb; }
}

// per-edge weight, written directly into CSR slot order
__global__ void k_edgew(const int* __restrict__ src, const int* __restrict__ dst) {
    int e = blockIdx.x * blockDim.x + threadIdx.x;
    if (e >= NE) return;
    int s = src[e], d = dst[e];
    float a = my_tanh(g_al[s] + g_ar[d]);
    g_w[g_cpos[e]] = a * g_norm[e];
}

// warp-per-dst-node CSR aggregation; h_out = sum_in(w * h_in[src]) + eps*raw
__global__ void k_agg(int hin_sel, int hout_sel) {
    int gt = blockIdx.x * blockDim.x + threadIdx.x;
    int n = gt >> 5;
    int lane = gt & 31;
    if (n >= NN) return;
    const float4* h4 = (const float4*)hsel(hin_sel);
    int beg = g_off[n], end = g_off[n + 1];
    float4 acc = make_float4(0.f, 0.f, 0.f, 0.f);
    for (int k = beg; k < end; k++) {
        int s = g_csrc[k];
        float w = g_w[k];
        float4 v = h4[(size_t)s * 32 + lane];
        acc.x = fmaf(w, v.x, acc.x);
        acc.y = fmaf(w, v.y, acc.y);
        acc.z = fmaf(w, v.z, acc.z);
        acc.w = fmaf(w, v.w, acc.w);
    }
    const float4* r4 = (const float4*)g_h0;
    float4 rv = r4[(size_t)n * 32 + lane];
    acc.x = fmaf(FAEPS, rv.x, acc.x);
    acc.y = fmaf(FAEPS, rv.y, acc.y);
    acc.z = fmaf(FAEPS, rv.z, acc.z);
    acc.w = fmaf(FAEPS, rv.w, acc.w);
    ((float4*)hsel(hout_sel))[(size_t)n * 32 + lane] = acc;
}

// ---------------- head: emb = h @ W2^T + b2; out = log_softmax(emb) -------
#define NPB 16
__global__ void k_head(int hin_sel, const float* __restrict__ W2,
                       const float* __restrict__ B2, float* __restrict__ out,
                       int write_emb) {
    __shared__ __align__(16) float Wsm[HID * OUTD];  // transposed: [k][o]
    __shared__ float Hsm[NPB * HID];
    __shared__ float Bsm[OUTD];
    int tid = threadIdx.x;
    const float* h = hsel(hin_sel);
    for (int idx = tid; idx < HID * OUTD; idx += 256) {
        int o = idx >> 7, k = idx & 127;
        Wsm[k * OUTD + o] = W2[idx];
    }
    if (tid < OUTD) Bsm[tid] = B2[tid];
    int node0 = blockIdx.x * NPB;
    for (int idx = tid; idx < NPB * HID; idx += 256) {
        int nl = idx >> 7, k = idx & 127;
        int n = node0 + nl;
        Hsm[idx] = (n < NN) ? h[(size_t)n * HID + k] : 0.0f;
    }
    __syncthreads();

    int nl = tid >> 4;        // node within block (0..15)
    int og = tid & 15;        // output group (4 outputs each)
    int n = node0 + nl;
    float acc0 = 0.f, acc1 = 0.f, acc2 = 0.f, acc3 = 0.f;
    const float4* W4 = (const float4*)Wsm;
    const float* hr = &Hsm[nl * HID];
#pragma unroll 4
    for (int k = 0; k < HID; k++) {
        float hv = hr[k];
        float4 wv = W4[k * 16 + og];
        acc0 = fmaf(hv, wv.x, acc0);
        acc1 = fmaf(hv, wv.y, acc1);
        acc2 = fmaf(hv, wv.z, acc2);
        acc3 = fmaf(hv, wv.w, acc3);
    }
    acc0 += Bsm[og * 4 + 0];
    acc1 += Bsm[og * 4 + 1];
    acc2 += Bsm[og * 4 + 2];
    acc3 += Bsm[og * 4 + 3];

    // log_softmax over the 16-lane group (each lane holds 4 of the 64 values)
    float m = fmaxf(fmaxf(acc0, acc1), fmaxf(acc2, acc3));
#pragma unroll
    for (int off = 8; off; off >>= 1)
        m = fmaxf(m, __shfl_xor_sync(0xffffffffu, m, off));
    float se = expf(acc0 - m) + expf(acc1 - m) + expf(acc2 - m) + expf(acc3 - m);
#pragma unroll
    for (int off = 8; off; off >>= 1)
        se += __shfl_xor_sync(0xffffffffu, se, off);
    float lse = m + logf(se);

    if (n < NN) {
        size_t base = (size_t)n * OUTD + og * 4;
        out[base + 0] = acc0 - lse;
        out[base + 1] = acc1 - lse;
        out[base + 2] = acc2 - lse;
        out[base + 3] = acc3 - lse;
        if (write_emb) {
            float* emb = out + (size_t)NN * OUTD;
            emb[base + 0] = acc0;
            emb[base + 1] = acc1;
            emb[base + 2] = acc2;
            emb[base + 3] = acc3;
        }
    }
}

// ---------------- launch ----------------
extern "C" void kernel_launch(void* const* d_in, const int* in_sizes, int n_in,
                              void* d_out, int out_size) {
    const float* x    = (const float*)d_in[0];
    const int*   ei   = (const int*)d_in[1];
    const int*   src  = ei;
    const int*   dst  = ei + NE;
    const float* t1w  = (const float*)d_in[2];
    const float* t1b  = (const float*)d_in[3];
    const float* t2w  = (const float*)d_in[4];
    const float* t2b  = (const float*)d_in[5];
    const float* attl = (const float*)d_in[6];
    const float* attr = (const float*)d_in[7];
    float* out = (float*)d_out;
    int write_emb = (out_size >= 2 * NN * OUTD) ? 1 : 0;

    const int TB = 256;
    int gN = (NN + TB - 1) / TB;
    int gE = (NE + TB - 1) / TB;
    int gW = (NN * 32 + TB - 1) / TB;   // warp-per-node grids

    k_zero<<<gN, TB>>>();
    k_hist<<<gE, TB>>>(dst);
    k_scan<<<1, 1024>>>();
    k_dinv<<<gN, TB>>>();
    k_fill<<<gE, TB>>>(src, dst);

    k_gemm1<<<(NN + 127) / 128, 256>>>(x, t1w, t1b);

    // layers: h0 -> ha -> hb -> ha  (raw = h0)
    int hin = 0;
    int hout_seq[3] = {1, 2, 1};
    for (int i = 0; i < 3; i++) {
        k_attn<<<gW, TB>>>(hin, attl + i * HID, attr + i * HID);
        k_edgew<<<gE, TB>>>(src, dst);
        k_agg<<<gW, TB>>>(hin, hout_seq[i]);
        hin = hout_seq[i];
    }

    k_head<<<(NN + NPB - 1) / NPB, 256>>>(hin, t2w, t2b, out, write_emb);
}

// round 3
// speedup vs baseline: 1.1926x; 1.1926x over previous
#include <cuda_runtime.h>
#include <math.h>
#include <stdint.h>

#define NN   50000
#define NE   600000
#define IND  512
#define HID  128
#define OUTD 64
#define FAEPS 0.1f

// ---------------- scratch (static device memory; no allocs) ----------------
__device__ __align__(256) int   g_cnt[NN];
__device__ __align__(256) int   g_cur[NN];
__device__ __align__(256) int   g_off[NN + 1];
__device__ __align__(256) int   g_csrc[NE];     // src per CSR slot
__device__ __align__(256) float g_normc[NE];    // gcn norm per CSR slot
__device__ __align__(256) float g_dinv[NN];
__device__ __align__(256) float g_h0[NN * HID]; // raw (post transform-1)
__device__ __align__(256) float g_ha[NN * HID];
__device__ __align__(256) float g_hb[NN * HID];
__device__ __align__(256) float g_alb[2][NN];
__device__ __align__(256) float g_arb[2][NN];

__device__ __forceinline__ float* hsel(int s) {
    return s == 0 ? g_h0 : (s == 1 ? g_ha : g_hb);
}

__device__ __forceinline__ float my_tanh(float x) {
    float e = expf(2.0f * x);
    return 1.0f - 2.0f / (e + 1.0f);
}

__device__ __forceinline__ uint32_t to_tf32u(float x) {
    uint32_t o;
    asm("cvt.rna.tf32.f32 %0, %1;" : "=r"(o) : "f"(x));
    return o;
}

__device__ __forceinline__ void mma_tf32(float* c, const uint32_t* a, const uint32_t* b) {
    asm volatile(
        "mma.sync.aligned.m16n8k8.row.col.f32.tf32.tf32.f32 "
        "{%0,%1,%2,%3}, {%4,%5,%6,%7}, {%8,%9}, {%0,%1,%2,%3};"
        : "+f"(c[0]), "+f"(c[1]), "+f"(c[2]), "+f"(c[3])
        : "r"(a[0]), "r"(a[1]), "r"(a[2]), "r"(a[3]), "r"(b[0]), "r"(b[1]));
}

// ---------------- graph preprocessing ----------------
__global__ void k_zero() {
    int i = blockIdx.x * blockDim.x + threadIdx.x;
    if (i < NN) { g_cnt[i] = 0; g_cur[i] = 0; }
}

__global__ void k_hist(const int* __restrict__ dst) {
    int e = blockIdx.x * blockDim.x + threadIdx.x;
    if (e < NE) atomicAdd(&g_cnt[dst[e]], 1);
}

// single-block exclusive scan over g_cnt -> g_off (+ dinv)
__global__ void k_scan() {
    __shared__ int sums[1024];
    int tid = threadIdx.x;
    int chunk = (NN + 1023) / 1024;
    int beg = tid * chunk;
    int end = beg + chunk; if (end > NN) end = NN;
    int s = 0;
    for (int i = beg; i < end; i++) s += g_cnt[i];
    sums[tid] = s;
    __syncthreads();
    for (int off = 1; off < 1024; off <<= 1) {
        int v = 0;
        if (tid >= off) v = sums[tid - off];
        __syncthreads();
        sums[tid] += v;
        __syncthreads();
    }
    int run = (tid == 0) ? 0 : sums[tid - 1];
    for (int i = beg; i < end; i++) {
        int c = g_cnt[i];
        g_off[i] = run; run += c;
        g_dinv[i] = (c > 0) ? rsqrtf((float)c) : 0.0f;
    }
    if (tid == 1023) g_off[NN] = sums[1023];
}

__global__ void k_fill(const int* __restrict__ src, const int* __restrict__ dst) {
    int e = blockIdx.x * blockDim.x + threadIdx.x;
    if (e >= NE) return;
    int s = src[e], d = dst[e];
    int slot = atomicAdd(&g_cur[d], 1);
    int k = g_off[d] + slot;
    g_csrc[k] = s;
    g_normc[k] = g_dinv[s] * g_dinv[d];
}

// ---------------- transform 1 via mma.sync tf32 ----------------
// C[128m x 128n] = X_tile @ W^T. 8 warps in 2x4 grid, 64x32 per warp.
// smem tiles 128x32 with stride 36 (bank = (4r+c)%32: conflict-free frags).
#define SMS 36
#define GM_NT 16   // 512/32 K tiles

__global__ __launch_bounds__(256) void k_gemm_tc(
    const float* __restrict__ X, const float* __restrict__ W,
    const float* __restrict__ B,
    const float* __restrict__ attl0, const float* __restrict__ attr0)
{
    __shared__ __align__(16) float As[128 * SMS];
    __shared__ __align__(16) float Bs[128 * SMS];
    __shared__ float s_pa[128], s_pb[128];

    int tid = threadIdx.x;
    int wid = tid >> 5, lane = tid & 31;
    int wr = wid >> 2, wc = wid & 3;      // warp grid 2x4
    int m0 = blockIdx.x * 128;
    int lq = lane >> 2;                    // 0..7
    int lr = lane & 3;                     // 0..3

    if (tid < 128) { s_pa[tid] = 0.f; s_pb[tid] = 0.f; }

    float acc[4][4][4];
#pragma unroll
    for (int i = 0; i < 4; i++)
#pragma unroll
        for (int j = 0; j < 4; j++)
#pragma unroll
            for (int k = 0; k < 4; k++) acc[i][j][k] = 0.f;

    // prefetch tile 0: each thread 4 float4 of A and B
    float4 ra[4], rb[4];
#pragma unroll
    for (int i = 0; i < 4; i++) {
        int j = tid + 256 * i;
        int row = j >> 3, kq = j & 7;
        int m = m0 + row;
        ra[i] = (m < NN) ? *(const float4*)(X + (size_t)m * IND + kq * 4)
                         : make_float4(0.f, 0.f, 0.f, 0.f);
        rb[i] = *(const float4*)(W + (size_t)row * IND + kq * 4);
    }

    for (int t = 0; t < GM_NT; t++) {
        if (t) __syncthreads();
#pragma unroll
        for (int i = 0; i < 4; i++) {
            int j = tid + 256 * i;
            int row = j >> 3, kq = j & 7;
            float* ap = As + row * SMS + kq * 4;
            float* bp = Bs + row * SMS + kq * 4;
            ap[0] = __uint_as_float(to_tf32u(ra[i].x));
            ap[1] = __uint_as_float(to_tf32u(ra[i].y));
            ap[2] = __uint_as_float(to_tf32u(ra[i].z));
            ap[3] = __uint_as_float(to_tf32u(ra[i].w));
            bp[0] = __uint_as_float(to_tf32u(rb[i].x));
            bp[1] = __uint_as_float(to_tf32u(rb[i].y));
            bp[2] = __uint_as_float(to_tf32u(rb[i].z));
            bp[3] = __uint_as_float(to_tf32u(rb[i].w));
        }
        __syncthreads();
        if (t + 1 < GM_NT) {
            const float* Xb = X + (t + 1) * 32;
            const float* Wb = W + (t + 1) * 32;
#pragma unroll
            for (int i = 0; i < 4; i++) {
                int j = tid + 256 * i;
                int row = j >> 3, kq = j & 7;
                int m = m0 + row;
                ra[i] = (m < NN) ? *(const float4*)(Xb + (size_t)m * IND + kq * 4)
                                 : make_float4(0.f, 0.f, 0.f, 0.f);
                rb[i] = *(const float4*)(Wb + (size_t)row * IND + kq * 4);
            }
        }
#pragma unroll
        for (int kk = 0; kk < 32; kk += 8) {
            uint32_t af[4][4], bf[4][2];
#pragma unroll
            for (int mt = 0; mt < 4; mt++) {
                const float* ap = As + (wr * 64 + mt * 16 + lq) * SMS + kk + lr;
                af[mt][0] = __float_as_uint(ap[0]);
                af[mt][1] = __float_as_uint(ap[8 * SMS]);
                af[mt][2] = __float_as_uint(ap[4]);
                af[mt][3] = __float_as_uint(ap[8 * SMS + 4]);
            }
#pragma unroll
            for (int nt = 0; nt < 4; nt++) {
                const float* bp = Bs + (wc * 32 + nt * 8 + lq) * SMS + kk + lr;
                bf[nt][0] = __float_as_uint(bp[0]);
                bf[nt][1] = __float_as_uint(bp[4]);
            }
#pragma unroll
            for (int mt = 0; mt < 4; mt++)
#pragma unroll
                for (int nt = 0; nt < 4; nt++)
                    mma_tf32(acc[mt][nt], af[mt], bf[nt]);
        }
    }
    __syncthreads();

    // epilogue: bias + relu, store h0, layer-0 attn row-dots via smem atomics
#pragma unroll
    for (int mt = 0; mt < 4; mt++) {
        int r0l = wr * 64 + mt * 16 + lq;   // local rows
        int r1l = r0l + 8;
        int m0r = m0 + r0l, m1r = m0 + r1l;
        float dl0 = 0.f, dr0 = 0.f, dl1 = 0.f, dr1 = 0.f;
#pragma unroll
        for (int nt = 0; nt < 4; nt++) {
            int c = wc * 32 + nt * 8 + 2 * lr;
            float b0 = __ldg(B + c), b1 = __ldg(B + c + 1);
            float al0 = __ldg(attl0 + c), al1 = __ldg(attl0 + c + 1);
            float ar0 = __ldg(attr0 + c), ar1 = __ldg(attr0 + c + 1);
            float v00 = acc[mt][nt][0] + b0; v00 = v00 > 0.f ? v00 : 0.f;
            float v01 = acc[mt][nt][1] + b1; v01 = v01 > 0.f ? v01 : 0.f;
            float v10 = acc[mt][nt][2] + b0; v10 = v10 > 0.f ? v10 : 0.f;
            float v11 = acc[mt][nt][3] + b1; v11 = v11 > 0.f ? v11 : 0.f;
            dl0 = fmaf(v00, al0, fmaf(v01, al1, dl0));
            dr0 = fmaf(v00, ar0, fmaf(v01, ar1, dr0));
            dl1 = fmaf(v10, al0, fmaf(v11, al1, dl1));
            dr1 = fmaf(v10, ar0, fmaf(v11, ar1, dr1));
            if (m0r < NN) *(float2*)(g_h0 + (size_t)m0r * HID + c) = make_float2(v00, v01);
            if (m1r < NN) *(float2*)(g_h0 + (size_t)m1r * HID + c) = make_float2(v10, v11);
        }
        atomicAdd(&s_pa[r0l], dl0); atomicAdd(&s_pb[r0l], dr0);
        atomicAdd(&s_pa[r1l], dl1); atomicAdd(&s_pb[r1l], dr1);
    }
    __syncthreads();
    if (tid < 128 && m0 + tid < NN) {
        g_alb[0][m0 + tid] = s_pa[tid];
        g_arb[0][m0 + tid] = s_pb[tid];
    }
}

// ---------------- fused aggregate: edge weights + CSR gather + next attn ---
__global__ void k_agg(int hin_sel, int hout_sel, int ab_in, int ab_out,
                      const float* __restrict__ attl, const float* __restrict__ attr,
                      int do_attn)
{
    int gt = blockIdx.x * blockDim.x + threadIdx.x;
    int n = gt >> 5;
    int lane = gt & 31;
    if (n >= NN) return;
    const float4* h4 = (const float4*)hsel(hin_sel);
    const float* al = g_alb[ab_in];
    float ar_n = g_arb[ab_in][n];
    int beg = g_off[n], end = g_off[n + 1];
    float4 acc = make_float4(0.f, 0.f, 0.f, 0.f);
    for (int k = beg; k < end; k++) {
        int s = g_csrc[k];
        float nm = g_normc[k];
        float w = my_tanh(__ldg(&al[s]) + ar_n) * nm;
        float4 v = h4[(size_t)s * 32 + lane];
        acc.x = fmaf(w, v.x, acc.x);
        acc.y = fmaf(w, v.y, acc.y);
        acc.z = fmaf(w, v.z, acc.z);
        acc.w = fmaf(w, v.w, acc.w);
    }
    const float4* r4 = (const float4*)g_h0;
    float4 rv = r4[(size_t)n * 32 + lane];
    acc.x = fmaf(FAEPS, rv.x, acc.x);
    acc.y = fmaf(FAEPS, rv.y, acc.y);
    acc.z = fmaf(FAEPS, rv.z, acc.z);
    acc.w = fmaf(FAEPS, rv.w, acc.w);
    ((float4*)hsel(hout_sel))[(size_t)n * 32 + lane] = acc;

    if (do_attn) {
        float4 la = *(const float4*)(attl + lane * 4);
        float4 ra2 = *(const float4*)(attr + lane * 4);
        float pa = acc.x * la.x + acc.y * la.y + acc.z * la.z + acc.w * la.w;
        float pb = acc.x * ra2.x + acc.y * ra2.y + acc.z * ra2.z + acc.w * ra2.w;
#pragma unroll
        for (int off = 16; off; off >>= 1) {
            pa += __shfl_xor_sync(0xffffffffu, pa, off);
            pb += __shfl_xor_sync(0xffffffffu, pb, off);
        }
        if (lane == 0) { g_alb[ab_out][n] = pa; g_arb[ab_out][n] = pb; }
    }
}

// ---------------- head: emb = h @ W2^T + b2; out = log_softmax(emb) -------
#define NPB 16
__global__ void k_head(int hin_sel, const float* __restrict__ W2,
                       const float* __restrict__ B2, float* __restrict__ out,
                       int write_emb) {
    __shared__ __align__(16) float Wsm[HID * OUTD];  // transposed: [k][o]
    __shared__ float Hsm[NPB * HID];
    __shared__ float Bsm[OUTD];
    int tid = threadIdx.x;
    const float* h = hsel(hin_sel);
    for (int idx = tid; idx < HID * OUTD; idx += 256) {
        int o = idx >> 7, k = idx & 127;
        Wsm[k * OUTD + o] = W2[idx];
    }
    if (tid < OUTD) Bsm[tid] = B2[tid];
    int node0 = blockIdx.x * NPB;
    for (int idx = tid; idx < NPB * HID; idx += 256) {
        int nl = idx >> 7, k = idx & 127;
        int n = node0 + nl;
        Hsm[idx] = (n < NN) ? h[(size_t)n * HID + k] : 0.0f;
    }
    __syncthreads();

    int nl = tid >> 4;
    int og = tid & 15;
    int n = node0 + nl;
    float acc0 = 0.f, acc1 = 0.f, acc2 = 0.f, acc3 = 0.f;
    const float4* W4 = (const float4*)Wsm;
    const float* hr = &Hsm[nl * HID];
#pragma unroll 4
    for (int k = 0; k < HID; k++) {
        float hv = hr[k];
        float4 wv = W4[k * 16 + og];
        acc0 = fmaf(hv, wv.x, acc0);
        acc1 = fmaf(hv, wv.y, acc1);
        acc2 = fmaf(hv, wv.z, acc2);
        acc3 = fmaf(hv, wv.w, acc3);
    }
    acc0 += Bsm[og * 4 + 0];
    acc1 += Bsm[og * 4 + 1];
    acc2 += Bsm[og * 4 + 2];
    acc3 += Bsm[og * 4 + 3];

    float m = fmaxf(fmaxf(acc0, acc1), fmaxf(acc2, acc3));
#pragma unroll
    for (int off = 8; off; off >>= 1)
        m = fmaxf(m, __shfl_xor_sync(0xffffffffu, m, off));
    float se = expf(acc0 - m) + expf(acc1 - m) + expf(acc2 - m) + expf(acc3 - m);
#pragma unroll
    for (int off = 8; off; off >>= 1)
        se += __shfl_xor_sync(0xffffffffu, se, off);
    float lse = m + logf(se);

    if (n < NN) {
        size_t base = (size_t)n * OUTD + og * 4;
        out[base + 0] = acc0 - lse;
        out[base + 1] = acc1 - lse;
        out[base + 2] = acc2 - lse;
        out[base + 3] = acc3 - lse;
        if (write_emb) {
            float* emb = out + (size_t)NN * OUTD;
            emb[base + 0] = acc0;
            emb[base + 1] = acc1;
            emb[base + 2] = acc2;
            emb[base + 3] = acc3;
        }
    }
}

// ---------------- launch ----------------
extern "C" void kernel_launch(void* const* d_in, const int* in_sizes, int n_in,
                              void* d_out, int out_size) {
    const float* x    = (const float*)d_in[0];
    const int*   ei   = (const int*)d_in[1];
    const int*   src  = ei;
    const int*   dst  = ei + NE;
    const float* t1w  = (const float*)d_in[2];
    const float* t1b  = (const float*)d_in[3];
    const float* t2w  = (const float*)d_in[4];
    const float* t2b  = (const float*)d_in[5];
    const float* attl = (const float*)d_in[6];
    const float* attr = (const float*)d_in[7];
    float* out = (float*)d_out;
    int write_emb = (out_size >= 2 * NN * OUTD) ? 1 : 0;

    const int TB = 256;
    int gN = (NN + TB - 1) / TB;
    int gE = (NE + TB - 1) / TB;
    int gW = (NN * 32 + TB - 1) / TB;   // warp-per-node grids

    k_zero<<<gN, TB>>>();
    k_hist<<<gE, TB>>>(dst);
    k_scan<<<1, 1024>>>();
    k_fill<<<gE, TB>>>(src, dst);

    k_gemm_tc<<<(NN + 127) / 128, 256>>>(x, t1w, t1b, attl, attr);

    // layers: h0 -> ha -> hb -> ha  (raw = h0); al/ar ping-pong buffers
    k_agg<<<gW, TB>>>(0, 1, 0, 1, attl + 1 * HID, attr + 1 * HID, 1);
    k_agg<<<gW, TB>>>(1, 2, 1, 0, attl + 2 * HID, attr + 2 * HID, 1);
    k_agg<<<gW, TB>>>(2, 1, 0, 0, attl, attr, 0);

    k_head<<<(NN + NPB - 1) / NPB, 256>>>(1, t2w, t2b, out, write_emb);
}